// round 16
// baseline (speedup 1.0000x reference)
#include <cuda_runtime.h>
#include <math.h>
#include <stdint.h>

typedef unsigned long long ull;

#define KA 12
#define HSZ 4608
#define INP 5024
#define EPSB 1e-5f
#define NPX 6912.f

// big gemm: 10 col-chunks x 512, 216 row-blocks x 64 rows; block-level split-K -> 10 chunks
#define CSZ 512
#define NCH 10
#define NRB 216
#define NCHF 10
// head gemm tiling
#define CSZ2 768
#define LSTR2 770
#define NCH2 6
#define HROWS 320

// scratch
__device__ __align__(16) float g_h1[KA*16*576];
__device__ __align__(16) float g_h2[KA*16*576];
__device__ __align__(16) float g_h3[KA*8*576];
__device__ float g_p1[72*16*2];
__device__ float g_p2[72*16*2];
__device__ float g_p3[72*8*2];
__device__ float g_op[192], g_om[192], g_mm[192];
__device__ __align__(16) float g_part[(size_t)NCHF*13824*KA];
__device__ __align__(16) float g_hp[6*HSZ*2];
__device__ __align__(16) float g_part2[(size_t)NCH2*HROWS*KA];

// grid barriers (sense-reversal; counter self-resets; sense toggles across graph replays)
__device__ volatile unsigned bc_sense = 0u;  __device__ unsigned bc_cnt = 0u;
__device__ volatile unsigned bp_sense = 0u;  __device__ unsigned bp_cnt = 0u;

__device__ __forceinline__ void gbar_full(volatile unsigned* sense, unsigned* cnt, unsigned nb){
    __threadfence();
    __syncthreads();
    if (threadIdx.x == 0){
        unsigned s = *sense;
        if (atomicAdd(cnt, 1u) == nb - 1u){
            *cnt = 0u; __threadfence(); *sense = s ^ 1u;
        } else {
            while (*sense == s) { }
        }
        __threadfence();
    }
    __syncthreads();
}

__device__ __forceinline__ ull pk2(float a, float b){ ull r; asm("mov.b64 %0,{%1,%2};":"=l"(r):"f"(a),"f"(b)); return r; }
__device__ __forceinline__ ull dup2(float a){ ull r; asm("mov.b64 %0,{%1,%1};":"=l"(r):"f"(a)); return r; }
__device__ __forceinline__ ull fma2(ull a, ull b, ull c){ ull d; asm("fma.rn.f32x2 %0,%1,%2,%3;":"=l"(d):"l"(a),"l"(b),"l"(c)); return d; }
__device__ __forceinline__ ull add2(ull a, ull b){ ull d; asm("add.rn.f32x2 %0,%1,%2;":"=l"(d):"l"(a),"l"(b)); return d; }
__device__ __forceinline__ uint32_t s2u(const void* p){
    uint32_t a; asm("{ .reg .u64 t; cvta.to.shared.u64 t, %1; cvt.u32.u64 %0, t; }":"=r"(a):"l"(p)); return a;
}

// ================= fused convs: 72 blocks x 384 thr, 3 phases + 2 grid barriers =================
// Branch-free conv inner loops via x-padded smem tiles (halo cols pre-zeroed).
__global__ __launch_bounds__(384) void k_convs(
    const float* __restrict__ x,  const float* __restrict__ w1,
    const float* __restrict__ p,  const float* __restrict__ m,
    const float* __restrict__ phys_w, const float* __restrict__ phys_b,
    const float* __restrict__ ment_w, const float* __restrict__ ment_b,
    const float* __restrict__ w2, const float* __restrict__ g1, const float* __restrict__ bb1,
    const float* __restrict__ w3, const float* __restrict__ g2, const float* __restrict__ bb2)
{
    __shared__ float SMB[8816];
    const int blk = blockIdx.x, tid = threadIdx.x;
    const int warp = tid>>5, lane = tid&31;
    const int b = blk / 6, strip = blk % 6;
    const int px96 = tid % 96, q = tid / 96;

    // ---------- P1: conv1 1x1 over (c,d), 4-way cd split + stats ----------
    {
        float* ws = SMB;                                  // 4096
        float* psum = SMB + 4096;                         // 3*16*96 = 4608  [j][o][px]
        float (*sred)[16][2] = (float(*)[16][2])(SMB + 8704);  // 3*32
        for (int i = tid; i < 4096; i += 384) ws[i] = w1[i];
        __syncthreads();
        int px = strip*96 + px96;
        float acc[16];
#pragma unroll
        for (int o = 0; o < 16; o++) acc[o] = 0.f;
        const float* xb = x + (size_t)b*147456 + px;
        const int cd0 = q*64;
#pragma unroll 16
        for (int k = 0; k < 64; k++){
            int cd = cd0 + k;
            float xv = xb[(size_t)cd*576];
#pragma unroll
            for (int o = 0; o < 16; o++) acc[o] += xv * ws[o*256+cd];
        }
        if (q > 0){
#pragma unroll
            for (int o = 0; o < 16; o++) psum[(q-1)*1536 + o*96 + px96] = acc[o];
        }
        __syncthreads();
        if (q == 0){
#pragma unroll
            for (int o = 0; o < 16; o++)
                acc[o] += psum[o*96+px96] + psum[1536+o*96+px96] + psum[3072+o*96+px96];
#pragma unroll
            for (int o = 0; o < 16; o++) g_h1[((size_t)b*16+o)*576 + px] = acc[o];
#pragma unroll
            for (int o = 0; o < 16; o++){
                float s = acc[o], qq = acc[o]*acc[o];
#pragma unroll
                for (int off = 16; off; off >>= 1){
                    s  += __shfl_xor_sync(0xffffffffu, s,  off);
                    qq += __shfl_xor_sync(0xffffffffu, qq, off);
                }
                if (lane == 0){ sred[warp][o][0] = s; sred[warp][o][1] = qq; }
            }
        }
        if (blk == 0 && tid < 192){
            int j = tid/16, t = tid%16;
            float s1 = phys_b[t], s2 = ment_b[t], s3 = ment_b[t];
            for (int k = 0; k < 16; k++){
                s1 += p[j*16+k] * phys_w[t*16+k];
                float mv = m[j*16+k];
                s2 += mv * ment_w[t*16+k];
                s3 += 0.9f * mv * ment_w[t*16+k];
            }
            g_op[tid] = fmaxf(s1, 0.f);
            g_om[tid] = fmaxf(s2, 0.f);
            g_mm[tid] = fmaxf(s3, 0.f);
        }
        __syncthreads();
        if (tid < 16){
            g_p1[blk*32 + tid*2+0] = sred[0][tid][0]+sred[1][tid][0]+sred[2][tid][0];
            g_p1[blk*32 + tid*2+1] = sred[0][tid][1]+sred[1][tid][1]+sred[2][tid][1];
        }
    }
    gbar_full(&bc_sense, &bc_cnt, 72u);

    // ---------- P2: bn1 + relu -> conv2 3x3 SAME (branch-free, x-padded) ----------
    {
        float (*in_s)[6][26] = (float(*)[6][26])SMB;      // 2496 (1-col halo each side)
        float* ws = SMB + 2496;                           // 2304
        float* sc = SMB + 4800;
        float* sh = SMB + 4816;
        float (*sred)[4][2] = (float(*)[4][2])(SMB + 4832);   // 12 warps x 4 ch
        const int ty = strip;
        if (tid < 16){
            float S = 0.f, Q = 0.f;
#pragma unroll
            for (int i = 0; i < 72; i++){ S += g_p1[i*32+tid*2]; Q += g_p1[i*32+tid*2+1]; }
            float mu = S/NPX, var = Q/NPX - mu*mu;
            float r = rsqrtf(var + EPSB) * g1[tid];
            sc[tid] = r; sh[tid] = bb1[tid] - mu*r;
        }
        for (int i = tid; i < 2304; i += 384) ws[i] = w2[i];
        for (int i = tid; i < 2496; i += 384) ((float*)in_s)[i] = 0.f;
        __syncthreads();
        int r0 = 4*ty - 1;
        for (int i = tid; i < 16*6*24; i += 384){
            int ci = i/144, rr = (i/24)%6, cc = i%24;
            int gy = r0 + rr; float v = 0.f;
            if (gy >= 0 && gy < 24)
                v = fmaxf(g_h1[((size_t)b*16+ci)*576 + gy*24 + cc]*sc[ci] + sh[ci], 0.f);
            in_s[ci][rr][cc+1] = v;
        }
        __syncthreads();
        int ly = px96/24, lx = px96%24, gy = 4*ty + ly;
        float acc[4];
#pragma unroll
        for (int j = 0; j < 4; j++) acc[j] = 0.f;
        for (int ci = 0; ci < 16; ci++){
#pragma unroll
            for (int ky = 0; ky < 3; ky++){
#pragma unroll
                for (int kx = 0; kx < 3; kx++){
                    float xv = in_s[ci][ly+ky][lx+kx];
#pragma unroll
                    for (int j = 0; j < 4; j++)
                        acc[j] += xv * ws[((4*q+j)*16+ci)*9 + ky*3 + kx];
                }
            }
        }
#pragma unroll
        for (int j = 0; j < 4; j++) g_h2[((size_t)b*16+4*q+j)*576 + gy*24 + lx] = acc[j];
#pragma unroll
        for (int j = 0; j < 4; j++){
            float s = acc[j], qq = acc[j]*acc[j];
#pragma unroll
            for (int off = 16; off; off >>= 1){
                s  += __shfl_xor_sync(0xffffffffu, s,  off);
                qq += __shfl_xor_sync(0xffffffffu, qq, off);
            }
            if (lane == 0){ sred[warp][j][0] = s; sred[warp][j][1] = qq; }
        }
        __syncthreads();
        if (tid < 16){
            int g = tid >> 2, j = tid & 3;
            float S = sred[3*g][j][0]+sred[3*g+1][j][0]+sred[3*g+2][j][0];
            float Q = sred[3*g][j][1]+sred[3*g+1][j][1]+sred[3*g+2][j][1];
            g_p2[blk*32 + tid*2+0] = S;
            g_p2[blk*32 + tid*2+1] = Q;
        }
    }
    gbar_full(&bc_sense, &bc_cnt, 72u);

    // ---------- P3: bn2 + relu -> conv3 5x5 SAME (branch-free, x-padded) ----------
    {
        float (*in_s)[8][28] = (float(*)[8][28])SMB;      // 3584 (2-col halo each side)
        float* ws = SMB + 3584;                           // 3200
        float* sc = SMB + 6784;
        float* sh = SMB + 6800;
        float (*sred)[2][2] = (float(*)[2][2])(SMB + 6816);   // 12 warps x 2 ch
        const int ty = strip;
        if (tid < 16){
            float S = 0.f, Q = 0.f;
#pragma unroll
            for (int i = 0; i < 72; i++){ S += g_p2[i*32+tid*2]; Q += g_p2[i*32+tid*2+1]; }
            float mu = S/NPX, var = Q/NPX - mu*mu;
            float r = rsqrtf(var + EPSB) * g2[tid];
            sc[tid] = r; sh[tid] = bb2[tid] - mu*r;
        }
        for (int i = tid; i < 3200; i += 384) ws[i] = w3[i];
        for (int i = tid; i < 3584; i += 384) ((float*)in_s)[i] = 0.f;
        __syncthreads();
        int r0 = 4*ty - 2;
        for (int i = tid; i < 16*8*24; i += 384){
            int ci = i/192, rr = (i/24)%8, cc = i%24;
            int gy = r0 + rr; float v = 0.f;
            if (gy >= 0 && gy < 24)
                v = fmaxf(g_h2[((size_t)b*16+ci)*576 + gy*24 + cc]*sc[ci] + sh[ci], 0.f);
            in_s[ci][rr][cc+2] = v;
        }
        __syncthreads();
        int ly = px96/24, lx = px96%24, gy = 4*ty + ly;
        float acc[2];
        acc[0] = 0.f; acc[1] = 0.f;
        for (int ci = 0; ci < 16; ci++){
#pragma unroll
            for (int ky = 0; ky < 5; ky++){
#pragma unroll
                for (int kx = 0; kx < 5; kx++){
                    float xv = in_s[ci][ly+ky][lx+kx];
                    acc[0] += xv * ws[((2*q  )*16+ci)*25 + ky*5 + kx];
                    acc[1] += xv * ws[((2*q+1)*16+ci)*25 + ky*5 + kx];
                }
            }
        }
#pragma unroll
        for (int j = 0; j < 2; j++) g_h3[((size_t)b*8+2*q+j)*576 + gy*24 + lx] = acc[j];
#pragma unroll
        for (int j = 0; j < 2; j++){
            float s = acc[j], qq = acc[j]*acc[j];
#pragma unroll
            for (int off = 16; off; off >>= 1){
                s  += __shfl_xor_sync(0xffffffffu, s,  off);
                qq += __shfl_xor_sync(0xffffffffu, qq, off);
            }
            if (lane == 0){ sred[warp][j][0] = s; sred[warp][j][1] = qq; }
        }
        __syncthreads();
        if (tid < 8){
            int g = tid >> 1, j = tid & 1;
            float S = sred[3*g][j][0]+sred[3*g+1][j][0]+sred[3*g+2][j][0];
            float Q = sred[3*g][j][1]+sred[3*g+1][j][1]+sred[3*g+2][j][1];
            g_p3[blk*16 + tid*2+0] = S;
            g_p3[blk*16 + tid*2+1] = Q;
        }
    }
}

// ---------- big weight-streaming GEMM (UNCHANGED from round 12 win) ----------
__global__ __launch_bounds__(128, 3) void k_gemm(
    const float* __restrict__ w_ih, const float* __restrict__ g3,
    const float* __restrict__ bb3,  const float* __restrict__ vis)
{
    __shared__ __align__(16) float ring[4][4][4][128];
    __shared__ ull sW[4][64][6];
    __shared__ float sc[8], sh[8];
    const int rblk = blockIdx.x, chunk = blockIdx.y, tid = threadIdx.x;
    const int warp = tid>>5, lane = tid&31;
    const int c0 = chunk * CSZ;
    const int csz = (INP - c0 < CSZ) ? (INP - c0) : CSZ;
    if (tid < 8){
        float S = 0.f, Q = 0.f;
#pragma unroll
        for (int i = 0; i < 72; i++){ S += g_p3[i*16+tid*2]; Q += g_p3[i*16+tid*2+1]; }
        float mu = S/NPX, var = Q/NPX - mu*mu;
        float r = rsqrtf(var + EPSB) * g3[tid];
        sc[tid] = r; sh[tid] = bb3[tid] - mu*r;
    }
    __syncthreads();

    const int cl = warp*128 + 4*lane;
    ull act[4][6];
#pragma unroll
    for (int i = 0; i < 4; i++){
        int c = cl + i;
        if (c >= csz){
#pragma unroll
            for (int pp = 0; pp < 6; pp++) act[i][pp] = 0ULL;
        } else {
            int gc = c0 + c;
            if (gc < 4608){
                int ch = gc/576, px = gc - ch*576;
                float r = sc[ch], t = sh[ch];
#pragma unroll
                for (int pp = 0; pp < 6; pp++){
                    float v0 = fmaxf(g_h3[((2*pp)*8+ch)*576 + px]*r + t, 0.f);
                    float v1 = fmaxf(g_h3[((2*pp+1)*8+ch)*576 + px]*r + t, 0.f);
                    act[i][pp] = pk2(v0, v1);
                }
            } else if (gc < 4624){
                int t = gc - 4608;
#pragma unroll
                for (int pp = 0; pp < 6; pp++)
                    act[i][pp] = pk2(g_op[(2*pp)*16+t], g_op[(2*pp+1)*16+t]);
            } else if (gc < 4640){
                int t = gc - 4624;
#pragma unroll
                for (int pp = 0; pp < 6; pp++)
                    act[i][pp] = pk2(g_om[(2*pp)*16+t], g_om[(2*pp+1)*16+t]);
            } else if (gc < 4832){
                int r = gc - 4640; float o = g_op[r]; int rv = r/16;
#pragma unroll
                for (int pp = 0; pp < 6; pp++)
                    act[i][pp] = pk2(vis[(2*pp)*12+rv]*o, vis[(2*pp+1)*12+rv]*o);
            } else {
                float v = g_mm[gc-4832];
#pragma unroll
                for (int pp = 0; pp < 6; pp++) act[i][pp] = dup2(v);
            }
        }
    }
    const int csrc = (cl <= csz-4) ? cl : (csz-4);

    const int gate = rblk / 72;
    const int gm = (gate==0) ? 0 : ((gate==1) ? 2 : 3);
    const int row0 = rblk*64 - gate*4608;
    const float* __restrict__ wr = w_ih + (size_t)(gm*4608 + row0)*INP + c0;
    const uint32_t ringbase = s2u(&ring[warp][0][0][0]);

    auto issue = [&](int g){
        const float* rp = wr + (size_t)(4*g)*INP + csrc;
        uint32_t d = ringbase + (uint32_t)((g & 3)*2048 + lane*16);
#pragma unroll
        for (int r = 0; r < 4; r++)
            asm volatile("cp.async.cg.shared.global [%0], [%1], 16;"
                         :: "r"(d + r*512), "l"(rp + (size_t)r*INP));
        asm volatile("cp.async.commit_group;");
    };
    issue(0); issue(1); issue(2);

    for (int p = 0; p < 16; p++){
        asm volatile("cp.async.wait_group 2;");
        const int sidx = p & 3;
        float4 W[4];
#pragma unroll
        for (int r = 0; r < 4; r++)
            W[r] = *(const float4*)&ring[warp][sidx][r][lane*4];
        if (p + 3 < 16) issue(p + 3);
        else asm volatile("cp.async.commit_group;");

        ull acc[4][6];
#pragma unroll
        for (int r = 0; r < 4; r++)
#pragma unroll
            for (int pp = 0; pp < 6; pp++) acc[r][pp] = 0ULL;
#pragma unroll
        for (int r = 0; r < 4; r++){
            ull w0 = dup2(W[r].x), w1 = dup2(W[r].y), w2 = dup2(W[r].z), w3 = dup2(W[r].w);
#pragma unroll
            for (int pp = 0; pp < 6; pp++){
                acc[r][pp] = fma2(w0, act[0][pp], acc[r][pp]);
                acc[r][pp] = fma2(w1, act[1][pp], acc[r][pp]);
                acc[r][pp] = fma2(w2, act[2][pp], acc[r][pp]);
                acc[r][pp] = fma2(w3, act[3][pp], acc[r][pp]);
            }
        }
        const bool hi16 = (lane & 16) != 0;
        ull t0[2][6];
#pragma unroll
        for (int pp = 0; pp < 6; pp++){
            ull g0 = hi16 ? acc[0][pp] : acc[2][pp];
            ull g1 = hi16 ? acc[1][pp] : acc[3][pp];
            t0[0][pp] = add2(hi16 ? acc[2][pp] : acc[0][pp], __shfl_xor_sync(0xffffffffu, g0, 16));
            t0[1][pp] = add2(hi16 ? acc[3][pp] : acc[1][pp], __shfl_xor_sync(0xffffffffu, g1, 16));
        }
        const bool hi8 = (lane & 8) != 0;
        ull t1[6];
#pragma unroll
        for (int pp = 0; pp < 6; pp++){
            ull g = hi8 ? t0[0][pp] : t0[1][pp];
            t1[pp] = add2(hi8 ? t0[1][pp] : t0[0][pp], __shfl_xor_sync(0xffffffffu, g, 8));
        }
        const bool hi4 = (lane & 4) != 0;
        ull t2[3];
#pragma unroll
        for (int j = 0; j < 3; j++){
            ull g = hi4 ? t1[j] : t1[j+3];
            t2[j] = add2(hi4 ? t1[j+3] : t1[j], __shfl_xor_sync(0xffffffffu, g, 4));
        }
#pragma unroll
        for (int off = 2; off; off >>= 1)
#pragma unroll
            for (int j = 0; j < 3; j++)
                t2[j] = add2(t2[j], __shfl_xor_sync(0xffffffffu, t2[j], off));
        int row = 4*p + (lane >> 3);
        int pairbase = (lane & 4) ? 3 : 0;
        int local = lane & 3;
        if (local < 3) sW[warp][row][pairbase + local] = t2[local];
    }
    asm volatile("cp.async.wait_group 0;");
    __syncthreads();
    for (int idx = tid; idx < 384; idx += 128){
        int row = idx/6, j = idx - row*6;
        ull v = add2(add2(sW[0][row][j], sW[1][row][j]), add2(sW[2][row][j], sW[3][row][j]));
        *(ull*)&g_part[((size_t)chunk*13824 + rblk*64 + row)*KA + j*2] = v;
    }
}

// ================= fused post: fin + head GEMM + finalize/action, 120 blocks x 128 =================
__global__ __launch_bounds__(128) void k_post(
    const float* __restrict__ b_ih, const float* __restrict__ b_hh,
    const float* __restrict__ ah_w, const float* __restrict__ inf_w,
    const float* __restrict__ ah_b, const float* __restrict__ inf_b,
    const float* __restrict__ act_w, const float* __restrict__ act_b,
    float* __restrict__ out)
{
    __shared__ __align__(16) ull lsu[6*LSTR2];
    const int blk = blockIdx.x, tid = threadIdx.x;

    for (int idx = blk*128 + tid; idx < KA*HSZ; idx += 120*128){
        int b = idx % KA, h = idx / KA;
        float si = b_ih[h] + b_hh[h];
        float sg = b_ih[9216 + h] + b_hh[9216 + h];
        float so = b_ih[13824 + h] + b_hh[13824 + h];
#pragma unroll
        for (int ch = 0; ch < NCHF; ch++){
            const float* pp = g_part + (size_t)ch*13824*KA;
            si += pp[(size_t)h*KA + b];
            sg += pp[(size_t)(4608 + h)*KA + b];
            so += pp[(size_t)(9216 + h)*KA + b];
        }
        float c  = (1.f/(1.f + __expf(-si))) * tanhf(sg);
        float hv = (1.f/(1.f + __expf(-so))) * tanhf(c);
        g_hp[((size_t)(b>>1)*HSZ + h)*2 + (b&1)] = fmaxf(hv, 0.f);
    }
    gbar_full(&bp_sense, &bp_cnt, 120u);

    {
        int rblk = blk % 20, chunk = blk / 20;
        int c0 = chunk * CSZ2;
        const ull* gsrc = (const ull*)g_hp;
        for (int i = tid; i < 6*CSZ2; i += 128){
            int pp = i/CSZ2, c = i - pp*CSZ2;
            lsu[pp*LSTR2 + c] = gsrc[(size_t)pp*HSZ + c0 + c];
        }
        __syncthreads();
        int warp = tid>>5, lane = tid&31;
        int cb = 2*lane;
        int ridx = rblk*16 + warp*4;
        const float* __restrict__ wb = (ridx < 128) ? ah_w + (size_t)ridx*HSZ + c0
                                                    : inf_w + (size_t)(ridx-128)*HSZ + c0;
        ull acc[4][6];
#pragma unroll
        for (int r = 0; r < 4; r++)
#pragma unroll
            for (int pp = 0; pp < 6; pp++) acc[r][pp] = 0ULL;
#pragma unroll
        for (int i = 0; i < 12; i++){
            int c = i*64 + cb;
            float2 wv0 = *(const float2*)(wb + c);
            float2 wv1 = *(const float2*)(wb + HSZ + c);
            float2 wv2 = *(const float2*)(wb + 2*HSZ + c);
            float2 wv3 = *(const float2*)(wb + 3*HSZ + c);
            ull W0x = dup2(wv0.x), W0y = dup2(wv0.y);
            ull W1x = dup2(wv1.x), W1y = dup2(wv1.y);
            ull W2x = dup2(wv2.x), W2y = dup2(wv2.y);
            ull W3x = dup2(wv3.x), W3y = dup2(wv3.y);
#pragma unroll
            for (int pp = 0; pp < 6; pp++){
                ulonglong2 lv = *(const ulonglong2*)&lsu[pp*LSTR2 + c];
                acc[0][pp] = fma2(W0x, lv.x, acc[0][pp]);
                acc[0][pp] = fma2(W0y, lv.y, acc[0][pp]);
                acc[1][pp] = fma2(W1x, lv.x, acc[1][pp]);
                acc[1][pp] = fma2(W1y, lv.y, acc[1][pp]);
                acc[2][pp] = fma2(W2x, lv.x, acc[2][pp]);
                acc[2][pp] = fma2(W2y, lv.y, acc[2][pp]);
                acc[3][pp] = fma2(W3x, lv.x, acc[3][pp]);
                acc[3][pp] = fma2(W3y, lv.y, acc[3][pp]);
            }
        }
#pragma unroll
        for (int r = 0; r < 4; r++)
#pragma unroll
            for (int pp = 0; pp < 6; pp++){
                ull v = acc[r][pp];
#pragma unroll
                for (int off = 16; off; off >>= 1)
                    v = add2(v, __shfl_xor_sync(0xffffffffu, v, off));
                acc[r][pp] = v;
            }
        if (lane < 12){
            int pp = lane>>1, hi = lane&1;
#pragma unroll
            for (int r = 0; r < 4; r++){
                float lo_, hi_;
                asm("mov.b64 {%0,%1}, %2;" : "=f"(lo_), "=f"(hi_) : "l"(acc[r][pp]));
                g_part2[((size_t)chunk*HROWS + ridx + r)*KA + lane] = hi ? hi_ : lo_;
            }
        }
    }

    __threadfence();
    __syncthreads();
    if (tid == 0){
        unsigned s = bp_sense;
        if (atomicAdd(&bp_cnt, 1u) == 119u){
            bp_cnt = 0u; __threadfence(); bp_sense = s ^ 1u;
        } else if (blk == 0){
            while (bp_sense == s) { }
        }
        __threadfence();
    }
    __syncthreads();
    if (blk != 0) return;

    float* t = (float*)lsu;
    for (int idx = tid; idx < HROWS*KA; idx += 128){
        int b = idx % KA, r = idx / KA;
        float s = (r < 128) ? ah_b[r] : inf_b[r-128];
#pragma unroll
        for (int ch = 0; ch < NCH2; ch++)
            s += g_part2[((size_t)ch*HROWS + r)*KA + b];
        if (r < 128) t[b*128 + r] = fmaxf(s, 0.f);
        else         out[192 + b*192 + (r-128)] = s;
    }
    __syncthreads();
    for (int i = tid; i < 192; i += 128){
        int b = i/16, a = i%16;
        float s = act_b[a];
        for (int q = 0; q < 128; q++) s += t[b*128+q] * act_w[a*128+q];
        out[b*16 + a] = s;
    }
}

extern "C" void kernel_launch(void* const* d_in, const int* in_sizes, int n_in,
                              void* d_out, int out_size){
    const float* x       = (const float*)d_in[0];
    const float* p       = (const float*)d_in[1];
    const float* m       = (const float*)d_in[2];
    const float* vis     = (const float*)d_in[3];
    const float* conv1_w = (const float*)d_in[4];
    const float* bn1_g   = (const float*)d_in[6];
    const float* bn1_b   = (const float*)d_in[7];
    const float* conv2_w = (const float*)d_in[8];
    const float* bn2_g   = (const float*)d_in[10];
    const float* bn2_b   = (const float*)d_in[11];
    const float* conv3_w = (const float*)d_in[12];
    const float* bn3_g   = (const float*)d_in[14];
    const float* bn3_b   = (const float*)d_in[15];
    const float* phys_w  = (const float*)d_in[16];
    const float* phys_b  = (const float*)d_in[17];
    const float* ment_w  = (const float*)d_in[18];
    const float* ment_b  = (const float*)d_in[19];
    const float* w_ih    = (const float*)d_in[20];   // w_hh (21) dead: h0 = 0
    const float* b_ih    = (const float*)d_in[22];
    const float* b_hh    = (const float*)d_in[23];
    const float* ah_w    = (const float*)d_in[24];
    const float* ah_b    = (const float*)d_in[25];
    const float* act_w   = (const float*)d_in[26];
    const float* act_b   = (const float*)d_in[27];
    const float* inf_w   = (const float*)d_in[28];
    const float* inf_b   = (const float*)d_in[29];
    float* out = (float*)d_out;

    k_convs<<<72, 384>>>(x, conv1_w, p, m, phys_w, phys_b, ment_w, ment_b,
                         conv2_w, bn1_g, bn1_b, conv3_w, bn2_g, bn2_b);         // 0
    k_gemm<<<dim3(NRB, NCH), 128>>>(w_ih, bn3_g, bn3_b, vis);                   // 1
    k_post<<<120, 128>>>(b_ih, b_hh, ah_w, inf_w, ah_b, inf_b,
                         act_w, act_b, out);                                    // 2
}

// round 17
// speedup vs baseline: 1.0370x; 1.0370x over previous
#include <cuda_runtime.h>
#include <math.h>
#include <stdint.h>

typedef unsigned long long ull;

#define KA 12
#define HSZ 4608
#define INP 5024
#define EPSB 1e-5f
#define NPX 6912.f

#define CSZ 512
#define NCH 10
#define NRB 216
#define NCHF 10
#define CSZ2 768
#define LSTR2 770
#define NCH2 6
#define HROWS 320
#define NCB 144

// scratch
__device__ __align__(16) float g_h1[KA*16*576];
__device__ __align__(16) float g_h2[KA*16*576];
__device__ __align__(16) float g_h3[KA*8*576];
__device__ float g_p1[NCB*16*2];
__device__ float g_p2[NCB*16*2];
__device__ float g_p3[NCB*8*2];
__device__ float g_op[192], g_om[192], g_mm[192];
__device__ __align__(16) float g_part[(size_t)NCHF*13824*KA];
__device__ __align__(16) float g_hp[6*HSZ*2];
__device__ __align__(16) float g_part2[(size_t)NCH2*HROWS*KA];

// grid barriers (sense-reversal; counter self-resets; sense toggles across graph replays)
__device__ volatile unsigned bc_sense = 0u;  __device__ unsigned bc_cnt = 0u;
__device__ volatile unsigned bp_sense = 0u;  __device__ unsigned bp_cnt = 0u;

__device__ __forceinline__ void gbar_full(volatile unsigned* sense, unsigned* cnt, unsigned nb){
    __threadfence();
    __syncthreads();
    if (threadIdx.x == 0){
        unsigned s = *sense;
        if (atomicAdd(cnt, 1u) == nb - 1u){
            *cnt = 0u; __threadfence(); *sense = s ^ 1u;
        } else {
            while (*sense == s) { }
        }
        __threadfence();
    }
    __syncthreads();
}

__device__ __forceinline__ ull pk2(float a, float b){ ull r; asm("mov.b64 %0,{%1,%2};":"=l"(r):"f"(a),"f"(b)); return r; }
__device__ __forceinline__ ull dup2(float a){ ull r; asm("mov.b64 %0,{%1,%1};":"=l"(r):"f"(a)); return r; }
__device__ __forceinline__ ull fma2(ull a, ull b, ull c){ ull d; asm("fma.rn.f32x2 %0,%1,%2,%3;":"=l"(d):"l"(a),"l"(b),"l"(c)); return d; }
__device__ __forceinline__ ull add2(ull a, ull b){ ull d; asm("add.rn.f32x2 %0,%1,%2;":"=l"(d):"l"(a),"l"(b)); return d; }
__device__ __forceinline__ uint32_t s2u(const void* p){
    uint32_t a; asm("{ .reg .u64 t; cvta.to.shared.u64 t, %1; cvt.u32.u64 %0, t; }":"=r"(a):"l"(p)); return a;
}

// ====== fused convs: 144 blocks x 384 thr (2-row strips), 3 phases + 2 grid barriers ======
__global__ __launch_bounds__(384) void k_convs(
    const float* __restrict__ x,  const float* __restrict__ w1,
    const float* __restrict__ p,  const float* __restrict__ m,
    const float* __restrict__ phys_w, const float* __restrict__ phys_b,
    const float* __restrict__ ment_w, const float* __restrict__ ment_b,
    const float* __restrict__ w2, const float* __restrict__ g1, const float* __restrict__ bb1,
    const float* __restrict__ w3, const float* __restrict__ g2, const float* __restrict__ bb2)
{
    __shared__ float SMB[9600];
    const int blk = blockIdx.x, tid = threadIdx.x;
    const int b = blk / 12, s12 = blk % 12;
    const int px48 = tid % 48, g = tid / 48;   // 8 groups of 48

    // ---------- P1: conv1 1x1 over (c,d), 8-way cd split (48-px strip) ----------
    {
        float* ws = SMB;                 // 4096
        float* psum = SMB + 4096;        // 7*768 = 5376
        for (int i = tid; i < 4096; i += 384) ws[i] = w1[i];
        __syncthreads();
        const int px = s12*48 + px48;
        float acc[16];
#pragma unroll
        for (int o = 0; o < 16; o++) acc[o] = 0.f;
        const float* xb = x + (size_t)b*147456 + px;
        const int cd0 = g*32;
#pragma unroll 16
        for (int k = 0; k < 32; k++){
            int cd = cd0 + k;
            float xv = xb[(size_t)cd*576];
#pragma unroll
            for (int o = 0; o < 16; o++) acc[o] += xv * ws[o*256+cd];
        }
        if (g > 0){
#pragma unroll
            for (int o = 0; o < 16; o++) psum[(g-1)*768 + o*48 + px48] = acc[o];
        }
        __syncthreads();
        if (g == 0){
#pragma unroll
            for (int o = 0; o < 16; o++){
#pragma unroll
                for (int j = 0; j < 7; j++) acc[o] += psum[j*768 + o*48 + px48];
                g_h1[((size_t)b*16+o)*576 + px] = acc[o];
            }
            // stats source (px-private slots; all reads above precede these writes per-thread)
#pragma unroll
            for (int o = 0; o < 16; o++){
                psum[o*48 + px48] = acc[o];
                psum[768 + o*48 + px48] = acc[o]*acc[o];
            }
        }
        if (blk == 0 && tid >= 96 && tid < 288){
            int i = tid - 96;
            int j = i/16, t = i%16;
            float s1 = phys_b[t], s2 = ment_b[t], s3 = ment_b[t];
            for (int k = 0; k < 16; k++){
                s1 += p[j*16+k] * phys_w[t*16+k];
                float mv = m[j*16+k];
                s2 += mv * ment_w[t*16+k];
                s3 += 0.9f * mv * ment_w[t*16+k];
            }
            g_op[i] = fmaxf(s1, 0.f);
            g_om[i] = fmaxf(s2, 0.f);
            g_mm[i] = fmaxf(s3, 0.f);
        }
        __syncthreads();
        if (tid < 16){
            float S = 0.f, Q = 0.f;
#pragma unroll
            for (int k = 0; k < 48; k++){
                S += psum[tid*48 + k];
                Q += psum[768 + tid*48 + k];
            }
            g_p1[blk*32 + tid*2+0] = S;
            g_p1[blk*32 + tid*2+1] = Q;
        }
    }
    gbar_full(&bc_sense, &bc_cnt, NCB);

    // ---------- P2: bn1+relu -> conv2 3x3 SAME (2-row strip, 8 ch-pair groups) ----------
    {
        float (*in_s)[4][26] = (float(*)[4][26])SMB;      // 1664
        float* ws = SMB + 1664;                           // 2304
        float* sc = SMB + 3968;
        float* sh = SMB + 3984;
        float* stS = SMB + 4000;                          // 768
        float* stQ = SMB + 4768;                          // 768
        if (tid < 16){
            float S = 0.f, Q = 0.f;
            for (int i = 0; i < NCB; i++){ S += g_p1[i*32+tid*2]; Q += g_p1[i*32+tid*2+1]; }
            float mu = S/NPX, var = Q/NPX - mu*mu;
            float r = rsqrtf(var + EPSB) * g1[tid];
            sc[tid] = r; sh[tid] = bb1[tid] - mu*r;
        }
        for (int i = tid; i < 2304; i += 384) ws[i] = w2[i];
        for (int i = tid; i < 1664; i += 384) ((float*)in_s)[i] = 0.f;
        __syncthreads();
        const int r0 = 2*s12 - 1;
        for (int i = tid; i < 16*4*24; i += 384){
            int ci = i/96, rr = (i/24)%4, cc = i%24;
            int gy = r0 + rr; float v = 0.f;
            if (gy >= 0 && gy < 24)
                v = fmaxf(g_h1[((size_t)b*16+ci)*576 + gy*24 + cc]*sc[ci] + sh[ci], 0.f);
            in_s[ci][rr][cc+1] = v;
        }
        __syncthreads();
        const int ly = px48/24, lx = px48%24, gy = 2*s12 + ly;
        float acc[2];
        acc[0] = 0.f; acc[1] = 0.f;
        for (int ci = 0; ci < 16; ci++){
#pragma unroll
            for (int ky = 0; ky < 3; ky++){
#pragma unroll
                for (int kx = 0; kx < 3; kx++){
                    float xv = in_s[ci][ly+ky][lx+kx];
                    acc[0] += xv * ws[((2*g  )*16+ci)*9 + ky*3 + kx];
                    acc[1] += xv * ws[((2*g+1)*16+ci)*9 + ky*3 + kx];
                }
            }
        }
#pragma unroll
        for (int j = 0; j < 2; j++){
            g_h2[((size_t)b*16+2*g+j)*576 + gy*24 + lx] = acc[j];
            stS[(2*g+j)*48 + px48] = acc[j];
            stQ[(2*g+j)*48 + px48] = acc[j]*acc[j];
        }
        __syncthreads();
        if (tid < 16){
            float S = 0.f, Q = 0.f;
#pragma unroll
            for (int k = 0; k < 48; k++){ S += stS[tid*48+k]; Q += stQ[tid*48+k]; }
            g_p2[blk*32 + tid*2+0] = S;
            g_p2[blk*32 + tid*2+1] = Q;
        }
    }
    gbar_full(&bc_sense, &bc_cnt, NCB);

    // ---------- P3: bn2+relu -> conv3 5x5 SAME (2-row strip, ci-half x ch-pair groups) ----------
    {
        float (*in_s)[6][28] = (float(*)[6][28])SMB;      // 2688
        float* ws = SMB + 2688;                           // 3200
        float* sc = SMB + 5888;
        float* sh = SMB + 5904;
        float* pc  = SMB + 5920;                          // 4*2*48 = 384 half-combine
        float* stS = SMB + 6304;                          // 8*48 = 384
        float* stQ = SMB + 6688;                          // 384
        if (tid < 16){
            float S = 0.f, Q = 0.f;
            for (int i = 0; i < NCB; i++){ S += g_p2[i*32+tid*2]; Q += g_p2[i*32+tid*2+1]; }
            float mu = S/NPX, var = Q/NPX - mu*mu;
            float r = rsqrtf(var + EPSB) * g2[tid];
            sc[tid] = r; sh[tid] = bb2[tid] - mu*r;
        }
        for (int i = tid; i < 3200; i += 384) ws[i] = w3[i];
        for (int i = tid; i < 2688; i += 384) ((float*)in_s)[i] = 0.f;
        __syncthreads();
        const int r0 = 2*s12 - 2;
        for (int i = tid; i < 16*6*24; i += 384){
            int ci = i/144, rr = (i/24)%6, cc = i%24;
            int gy = r0 + rr; float v = 0.f;
            if (gy >= 0 && gy < 24)
                v = fmaxf(g_h2[((size_t)b*16+ci)*576 + gy*24 + cc]*sc[ci] + sh[ci], 0.f);
            in_s[ci][rr][cc+2] = v;
        }
        __syncthreads();
        const int ly = px48/24, lx = px48%24, gy = 2*s12 + ly;
        const int cg = g & 3, cih = g >> 2;
        float acc[2];
        acc[0] = 0.f; acc[1] = 0.f;
        for (int ci = cih*8; ci < cih*8+8; ci++){
#pragma unroll
            for (int ky = 0; ky < 5; ky++){
#pragma unroll
                for (int kx = 0; kx < 5; kx++){
                    float xv = in_s[ci][ly+ky][lx+kx];
                    acc[0] += xv * ws[((2*cg  )*16+ci)*25 + ky*5 + kx];
                    acc[1] += xv * ws[((2*cg+1)*16+ci)*25 + ky*5 + kx];
                }
            }
        }
        if (cih == 1){
            pc[(cg*2+0)*48 + px48] = acc[0];
            pc[(cg*2+1)*48 + px48] = acc[1];
        }
        __syncthreads();
        if (cih == 0){
            acc[0] += pc[(cg*2+0)*48 + px48];
            acc[1] += pc[(cg*2+1)*48 + px48];
#pragma unroll
            for (int j = 0; j < 2; j++){
                g_h3[((size_t)b*8+2*cg+j)*576 + gy*24 + lx] = acc[j];
                stS[(2*cg+j)*48 + px48] = acc[j];
                stQ[(2*cg+j)*48 + px48] = acc[j]*acc[j];
            }
        }
        __syncthreads();
        if (tid < 8){
            float S = 0.f, Q = 0.f;
#pragma unroll
            for (int k = 0; k < 48; k++){ S += stS[tid*48+k]; Q += stQ[tid*48+k]; }
            g_p3[blk*16 + tid*2+0] = S;
            g_p3[blk*16 + tid*2+1] = Q;
        }
    }
}

// ---------- big weight-streaming GEMM (mainloop unchanged; bn3 partial loop 144) ----------
__global__ __launch_bounds__(128, 3) void k_gemm(
    const float* __restrict__ w_ih, const float* __restrict__ g3,
    const float* __restrict__ bb3,  const float* __restrict__ vis)
{
    __shared__ __align__(16) float ring[4][4][4][128];
    __shared__ ull sW[4][64][6];
    __shared__ float sc[8], sh[8];
    const int rblk = blockIdx.x, chunk = blockIdx.y, tid = threadIdx.x;
    const int warp = tid>>5, lane = tid&31;
    const int c0 = chunk * CSZ;
    const int csz = (INP - c0 < CSZ) ? (INP - c0) : CSZ;
    if (tid < 8){
        float S = 0.f, Q = 0.f;
        for (int i = 0; i < NCB; i++){ S += g_p3[i*16+tid*2]; Q += g_p3[i*16+tid*2+1]; }
        float mu = S/NPX, var = Q/NPX - mu*mu;
        float r = rsqrtf(var + EPSB) * g3[tid];
        sc[tid] = r; sh[tid] = bb3[tid] - mu*r;
    }
    __syncthreads();

    const int cl = warp*128 + 4*lane;
    ull act[4][6];
#pragma unroll
    for (int i = 0; i < 4; i++){
        int c = cl + i;
        if (c >= csz){
#pragma unroll
            for (int pp = 0; pp < 6; pp++) act[i][pp] = 0ULL;
        } else {
            int gc = c0 + c;
            if (gc < 4608){
                int ch = gc/576, px = gc - ch*576;
                float r = sc[ch], t = sh[ch];
#pragma unroll
                for (int pp = 0; pp < 6; pp++){
                    float v0 = fmaxf(g_h3[((2*pp)*8+ch)*576 + px]*r + t, 0.f);
                    float v1 = fmaxf(g_h3[((2*pp+1)*8+ch)*576 + px]*r + t, 0.f);
                    act[i][pp] = pk2(v0, v1);
                }
            } else if (gc < 4624){
                int t = gc - 4608;
#pragma unroll
                for (int pp = 0; pp < 6; pp++)
                    act[i][pp] = pk2(g_op[(2*pp)*16+t], g_op[(2*pp+1)*16+t]);
            } else if (gc < 4640){
                int t = gc - 4624;
#pragma unroll
                for (int pp = 0; pp < 6; pp++)
                    act[i][pp] = pk2(g_om[(2*pp)*16+t], g_om[(2*pp+1)*16+t]);
            } else if (gc < 4832){
                int r = gc - 4640; float o = g_op[r]; int rv = r/16;
#pragma unroll
                for (int pp = 0; pp < 6; pp++)
                    act[i][pp] = pk2(vis[(2*pp)*12+rv]*o, vis[(2*pp+1)*12+rv]*o);
            } else {
                float v = g_mm[gc-4832];
#pragma unroll
                for (int pp = 0; pp < 6; pp++) act[i][pp] = dup2(v);
            }
        }
    }
    const int csrc = (cl <= csz-4) ? cl : (csz-4);

    const int gate = rblk / 72;
    const int gm = (gate==0) ? 0 : ((gate==1) ? 2 : 3);
    const int row0 = rblk*64 - gate*4608;
    const float* __restrict__ wr = w_ih + (size_t)(gm*4608 + row0)*INP + c0;
    const uint32_t ringbase = s2u(&ring[warp][0][0][0]);

    auto issue = [&](int g){
        const float* rp = wr + (size_t)(4*g)*INP + csrc;
        uint32_t d = ringbase + (uint32_t)((g & 3)*2048 + lane*16);
#pragma unroll
        for (int r = 0; r < 4; r++)
            asm volatile("cp.async.cg.shared.global [%0], [%1], 16;"
                         :: "r"(d + r*512), "l"(rp + (size_t)r*INP));
        asm volatile("cp.async.commit_group;");
    };
    issue(0); issue(1); issue(2);

    for (int p = 0; p < 16; p++){
        asm volatile("cp.async.wait_group 2;");
        const int sidx = p & 3;
        float4 W[4];
#pragma unroll
        for (int r = 0; r < 4; r++)
            W[r] = *(const float4*)&ring[warp][sidx][r][lane*4];
        if (p + 3 < 16) issue(p + 3);
        else asm volatile("cp.async.commit_group;");

        ull acc[4][6];
#pragma unroll
        for (int r = 0; r < 4; r++)
#pragma unroll
            for (int pp = 0; pp < 6; pp++) acc[r][pp] = 0ULL;
#pragma unroll
        for (int r = 0; r < 4; r++){
            ull w0 = dup2(W[r].x), w1 = dup2(W[r].y), w2 = dup2(W[r].z), w3 = dup2(W[r].w);
#pragma unroll
            for (int pp = 0; pp < 6; pp++){
                acc[r][pp] = fma2(w0, act[0][pp], acc[r][pp]);
                acc[r][pp] = fma2(w1, act[1][pp], acc[r][pp]);
                acc[r][pp] = fma2(w2, act[2][pp], acc[r][pp]);
                acc[r][pp] = fma2(w3, act[3][pp], acc[r][pp]);
            }
        }
        const bool hi16 = (lane & 16) != 0;
        ull t0[2][6];
#pragma unroll
        for (int pp = 0; pp < 6; pp++){
            ull g0 = hi16 ? acc[0][pp] : acc[2][pp];
            ull g1 = hi16 ? acc[1][pp] : acc[3][pp];
            t0[0][pp] = add2(hi16 ? acc[2][pp] : acc[0][pp], __shfl_xor_sync(0xffffffffu, g0, 16));
            t0[1][pp] = add2(hi16 ? acc[3][pp] : acc[1][pp], __shfl_xor_sync(0xffffffffu, g1, 16));
        }
        const bool hi8 = (lane & 8) != 0;
        ull t1[6];
#pragma unroll
        for (int pp = 0; pp < 6; pp++){
            ull g = hi8 ? t0[0][pp] : t0[1][pp];
            t1[pp] = add2(hi8 ? t0[1][pp] : t0[0][pp], __shfl_xor_sync(0xffffffffu, g, 8));
        }
        const bool hi4 = (lane & 4) != 0;
        ull t2[3];
#pragma unroll
        for (int j = 0; j < 3; j++){
            ull g = hi4 ? t1[j] : t1[j+3];
            t2[j] = add2(hi4 ? t1[j+3] : t1[j], __shfl_xor_sync(0xffffffffu, g, 4));
        }
#pragma unroll
        for (int off = 2; off; off >>= 1)
#pragma unroll
            for (int j = 0; j < 3; j++)
                t2[j] = add2(t2[j], __shfl_xor_sync(0xffffffffu, t2[j], off));
        int row = 4*p + (lane >> 3);
        int pairbase = (lane & 4) ? 3 : 0;
        int local = lane & 3;
        if (local < 3) sW[warp][row][pairbase + local] = t2[local];
    }
    asm volatile("cp.async.wait_group 0;");
    __syncthreads();
    for (int idx = tid; idx < 384; idx += 128){
        int row = idx/6, j = idx - row*6;
        ull v = add2(add2(sW[0][row][j], sW[1][row][j]), add2(sW[2][row][j], sW[3][row][j]));
        *(ull*)&g_part[((size_t)chunk*13824 + rblk*64 + row)*KA + j*2] = v;
    }
}

// ================= fused post (unchanged): fin + head GEMM + finalize/action =================
__global__ __launch_bounds__(128) void k_post(
    const float* __restrict__ b_ih, const float* __restrict__ b_hh,
    const float* __restrict__ ah_w, const float* __restrict__ inf_w,
    const float* __restrict__ ah_b, const float* __restrict__ inf_b,
    const float* __restrict__ act_w, const float* __restrict__ act_b,
    float* __restrict__ out)
{
    __shared__ __align__(16) ull lsu[6*LSTR2];
    const int blk = blockIdx.x, tid = threadIdx.x;

    for (int idx = blk*128 + tid; idx < KA*HSZ; idx += 120*128){
        int b = idx % KA, h = idx / KA;
        float si = b_ih[h] + b_hh[h];
        float sg = b_ih[9216 + h] + b_hh[9216 + h];
        float so = b_ih[13824 + h] + b_hh[13824 + h];
#pragma unroll
        for (int ch = 0; ch < NCHF; ch++){
            const float* pp = g_part + (size_t)ch*13824*KA;
            si += pp[(size_t)h*KA + b];
            sg += pp[(size_t)(4608 + h)*KA + b];
            so += pp[(size_t)(9216 + h)*KA + b];
        }
        float c  = (1.f/(1.f + __expf(-si))) * tanhf(sg);
        float hv = (1.f/(1.f + __expf(-so))) * tanhf(c);
        g_hp[((size_t)(b>>1)*HSZ + h)*2 + (b&1)] = fmaxf(hv, 0.f);
    }
    gbar_full(&bp_sense, &bp_cnt, 120u);

    {
        int rblk = blk % 20, chunk = blk / 20;
        int c0 = chunk * CSZ2;
        const ull* gsrc = (const ull*)g_hp;
        for (int i = tid; i < 6*CSZ2; i += 128){
            int pp = i/CSZ2, c = i - pp*CSZ2;
            lsu[pp*LSTR2 + c] = gsrc[(size_t)pp*HSZ + c0 + c];
        }
        __syncthreads();
        int warp = tid>>5, lane = tid&31;
        int cb = 2*lane;
        int ridx = rblk*16 + warp*4;
        const float* __restrict__ wb = (ridx < 128) ? ah_w + (size_t)ridx*HSZ + c0
                                                    : inf_w + (size_t)(ridx-128)*HSZ + c0;
        ull acc[4][6];
#pragma unroll
        for (int r = 0; r < 4; r++)
#pragma unroll
            for (int pp = 0; pp < 6; pp++) acc[r][pp] = 0ULL;
#pragma unroll
        for (int i = 0; i < 12; i++){
            int c = i*64 + cb;
            float2 wv0 = *(const float2*)(wb + c);
            float2 wv1 = *(const float2*)(wb + HSZ + c);
            float2 wv2 = *(const float2*)(wb + 2*HSZ + c);
            float2 wv3 = *(const float2*)(wb + 3*HSZ + c);
            ull W0x = dup2(wv0.x), W0y = dup2(wv0.y);
            ull W1x = dup2(wv1.x), W1y = dup2(wv1.y);
            ull W2x = dup2(wv2.x), W2y = dup2(wv2.y);
            ull W3x = dup2(wv3.x), W3y = dup2(wv3.y);
#pragma unroll
            for (int pp = 0; pp < 6; pp++){
                ulonglong2 lv = *(const ulonglong2*)&lsu[pp*LSTR2 + c];
                acc[0][pp] = fma2(W0x, lv.x, acc[0][pp]);
                acc[0][pp] = fma2(W0y, lv.y, acc[0][pp]);
                acc[1][pp] = fma2(W1x, lv.x, acc[1][pp]);
                acc[1][pp] = fma2(W1y, lv.y, acc[1][pp]);
                acc[2][pp] = fma2(W2x, lv.x, acc[2][pp]);
                acc[2][pp] = fma2(W2y, lv.y, acc[2][pp]);
                acc[3][pp] = fma2(W3x, lv.x, acc[3][pp]);
                acc[3][pp] = fma2(W3y, lv.y, acc[3][pp]);
            }
        }
#pragma unroll
        for (int r = 0; r < 4; r++)
#pragma unroll
            for (int pp = 0; pp < 6; pp++){
                ull v = acc[r][pp];
#pragma unroll
                for (int off = 16; off; off >>= 1)
                    v = add2(v, __shfl_xor_sync(0xffffffffu, v, off));
                acc[r][pp] = v;
            }
        if (lane < 12){
            int pp = lane>>1, hi = lane&1;
#pragma unroll
            for (int r = 0; r < 4; r++){
                float lo_, hi_;
                asm("mov.b64 {%0,%1}, %2;" : "=f"(lo_), "=f"(hi_) : "l"(acc[r][pp]));
                g_part2[((size_t)chunk*HROWS + ridx + r)*KA + lane] = hi ? hi_ : lo_;
            }
        }
    }

    __threadfence();
    __syncthreads();
    if (tid == 0){
        unsigned s = bp_sense;
        if (atomicAdd(&bp_cnt, 1u) == 119u){
            bp_cnt = 0u; __threadfence(); bp_sense = s ^ 1u;
        } else if (blk == 0){
            while (bp_sense == s) { }
        }
        __threadfence();
    }
    __syncthreads();
    if (blk != 0) return;

    float* t = (float*)lsu;
    for (int idx = tid; idx < HROWS*KA; idx += 128){
        int b = idx % KA, r = idx / KA;
        float s = (r < 128) ? ah_b[r] : inf_b[r-128];
#pragma unroll
        for (int ch = 0; ch < NCH2; ch++)
            s += g_part2[((size_t)ch*HROWS + r)*KA + b];
        if (r < 128) t[b*128 + r] = fmaxf(s, 0.f);
        else         out[192 + b*192 + (r-128)] = s;
    }
    __syncthreads();
    for (int i = tid; i < 192; i += 128){
        int b = i/16, a = i%16;
        float s = act_b[a];
        for (int q = 0; q < 128; q++) s += t[b*128+q] * act_w[a*128+q];
        out[b*16 + a] = s;
    }
}

extern "C" void kernel_launch(void* const* d_in, const int* in_sizes, int n_in,
                              void* d_out, int out_size){
    const float* x       = (const float*)d_in[0];
    const float* p       = (const float*)d_in[1];
    const float* m       = (const float*)d_in[2];
    const float* vis     = (const float*)d_in[3];
    const float* conv1_w = (const float*)d_in[4];
    const float* bn1_g   = (const float*)d_in[6];
    const float* bn1_b   = (const float*)d_in[7];
    const float* conv2_w = (const float*)d_in[8];
    const float* bn2_g   = (const float*)d_in[10];
    const float* bn2_b   = (const float*)d_in[11];
    const float* conv3_w = (const float*)d_in[12];
    const float* bn3_g   = (const float*)d_in[14];
    const float* bn3_b   = (const float*)d_in[15];
    const float* phys_w  = (const float*)d_in[16];
    const float* phys_b  = (const float*)d_in[17];
    const float* ment_w  = (const float*)d_in[18];
    const float* ment_b  = (const float*)d_in[19];
    const float* w_ih    = (const float*)d_in[20];   // w_hh (21) dead: h0 = 0
    const float* b_ih    = (const float*)d_in[22];
    const float* b_hh    = (const float*)d_in[23];
    const float* ah_w    = (const float*)d_in[24];
    const float* ah_b    = (const float*)d_in[25];
    const float* act_w   = (const float*)d_in[26];
    const float* act_b   = (const float*)d_in[27];
    const float* inf_w   = (const float*)d_in[28];
    const float* inf_b   = (const float*)d_in[29];
    float* out = (float*)d_out;

    k_convs<<<NCB, 384>>>(x, conv1_w, p, m, phys_w, phys_b, ment_w, ment_b,
                          conv2_w, bn1_g, bn1_b, conv3_w, bn2_g, bn2_b);        // 0
    k_gemm<<<dim3(NRB, NCH), 128>>>(w_ih, bn3_g, bn3_b, vis);                   // 1
    k_post<<<120, 128>>>(b_ih, b_hh, ah_w, inf_w, ah_b, inf_b,
                         act_w, act_b, out);                                    // 2
}